// round 1
// baseline (speedup 1.0000x reference)
#include <cuda_runtime.h>
#include <cuda_bf16.h>

// Dense 3x3 conv, NCHW fp32, stride 1, pad 1, + bias.
// x: (32,128,56,56), w: (256,128,3,3), bias: (256) -> out: (32,256,56,56)
//
// Block: 64 output channels x 8x8 spatial tile of one image.
// Grid: (49 spatial tiles, 4 oc tiles, 32 images).
// K loop over input channels in chunks of CK=8 staged in shared memory.
// Per-thread microtile: 4 oc x (2x2) px, 4x4 input patch cached in regs.

#define CK       8
#define TILE_OC  64
#define THREADS  256

__global__ __launch_bounds__(THREADS, 2)
void conv3x3_kernel(const float* __restrict__ x,
                    const float* __restrict__ w,
                    const float* __restrict__ bias,
                    float* __restrict__ out)
{
    // sW[r][oc]: r = c*9 + kh*3 + kw  (72 rows), oc padded 64->80 words.
    // Pad 80: STS stride 80 words -> bank stride 16 -> only 2-way write
    // conflict, and row stride 320B keeps float4 LDS.128 reads 16B-aligned.
    __shared__ float sW[CK * 9][80];
    __shared__ float sIn[CK][10][10];

    const int tid = threadIdx.x;
    // px-fastest warp layout: weight LDS broadcasts across the 16 px threads,
    // STG addresses within a warp land in few 32B sectors.
    const int pxg = tid & 15;          // 0..15 -> 2x2 px group
    const int ocg = tid >> 4;          // 0..15 -> 4 oc group
    const int gy  = pxg >> 2;
    const int gx  = pxg & 3;
    const int py  = gy * 2;            // local output row base (0,2,4,6)
    const int px  = gx * 2;            // local output col base
    const int ocb = ocg * 4;           // local oc base

    const int tile = blockIdx.x;       // 0..48
    const int th   = tile / 7;
    const int tw   = tile - th * 7;
    const int o0   = blockIdx.y * TILE_OC;
    const int n    = blockIdx.z;

    const int h0 = th * 8;
    const int w0 = tw * 8;

    const float* xn = x + (size_t)n * 128 * 56 * 56;

    float acc[4][4];                   // [oc][py*2+px]
#pragma unroll
    for (int i = 0; i < 4; ++i)
#pragma unroll
        for (int j = 0; j < 4; ++j) acc[i][j] = 0.0f;

    for (int c0 = 0; c0 < 128; c0 += CK) {
        // ---- stage input tile (CK x 10 x 10, zero-padded halo) ----
#pragma unroll
        for (int idx = tid; idx < CK * 100; idx += THREADS) {
            int c = idx / 100;
            int rem = idx - c * 100;
            int r = rem / 10;
            int q = rem - r * 10;
            int gh = h0 - 1 + r;
            int gw = w0 - 1 + q;
            float v = 0.0f;
            if ((unsigned)gh < 56u && (unsigned)gw < 56u)
                v = xn[((size_t)(c0 + c) * 56 + gh) * 56 + gw];
            sIn[c][r][q] = v;
        }
        // ---- stage weights (oc-major index -> coalesced 72-float gmem runs) ----
#pragma unroll
        for (int idx = tid; idx < CK * 9 * TILE_OC; idx += THREADS) {
            int oc = idx / (CK * 9);
            int r  = idx - oc * (CK * 9);
            sW[r][oc] = w[(size_t)(o0 + oc) * 1152 + c0 * 9 + r];
        }
        __syncthreads();

        // ---- microkernel: FMA-pipe bound (25 LDS per 144 FFMA per c) ----
#pragma unroll
        for (int c = 0; c < CK; ++c) {
            float xv[4][4];
#pragma unroll
            for (int iy = 0; iy < 4; ++iy)
#pragma unroll
                for (int ix = 0; ix < 4; ++ix)
                    xv[iy][ix] = sIn[c][py + iy][px + ix];

#pragma unroll
            for (int kh = 0; kh < 3; ++kh) {
#pragma unroll
                for (int kw = 0; kw < 3; ++kw) {
                    const float4 wv =
                        *(const float4*)&sW[c * 9 + kh * 3 + kw][ocb];
#pragma unroll
                    for (int oy = 0; oy < 2; ++oy) {
#pragma unroll
                        for (int ox = 0; ox < 2; ++ox) {
                            const float xs = xv[oy + kh][ox + kw];
                            const int j = oy * 2 + ox;
                            acc[0][j] = fmaf(wv.x, xs, acc[0][j]);
                            acc[1][j] = fmaf(wv.y, xs, acc[1][j]);
                            acc[2][j] = fmaf(wv.z, xs, acc[2][j]);
                            acc[3][j] = fmaf(wv.w, xs, acc[3][j]);
                        }
                    }
                }
            }
        }
        __syncthreads();
    }

    // ---- epilogue: +bias, store ----
#pragma unroll
    for (int i = 0; i < 4; ++i) {
        const int o = o0 + ocb + i;
        const float b = __ldg(&bias[o]);
        float* op = out + (((size_t)n * 256 + o) * 56 + h0) * 56 + w0;
#pragma unroll
        for (int oy = 0; oy < 2; ++oy)
#pragma unroll
            for (int ox = 0; ox < 2; ++ox)
                op[(py + oy) * 56 + (px + ox)] = acc[i][oy * 2 + ox] + b;
    }
}

extern "C" void kernel_launch(void* const* d_in, const int* in_sizes, int n_in,
                              void* d_out, int out_size)
{
    const float* x    = (const float*)d_in[0];
    const float* w    = (const float*)d_in[1];
    const float* bias = (const float*)d_in[2];
    float* out        = (float*)d_out;

    dim3 grid(49, 4, 32);
    conv3x3_kernel<<<grid, THREADS>>>(x, w, bias, out);
}

// round 2
// speedup vs baseline: 1.1357x; 1.1357x over previous
#include <cuda_runtime.h>
#include <cuda_bf16.h>

// Dense 3x3 conv, NCHW fp32, stride 1, pad 1, + bias.
// x: (32,128,56,56), w: (256,128,3,3), bias: (256) -> out: (32,256,56,56)
//
// Block: 64 oc x (8 rows x 16 cols) spatial tile, one image. 256 threads.
// Thread microtile: 4 oc x 2 rows x 4 px (32 outputs), accumulated as
// packed f32x2 pairs over adjacent px via fma.rn.f32x2 (FFMA2).
// Grid: (7 row-tiles * 4 col-tiles, 4 oc-tiles, 32 images). Col tile 16
// overhangs 56 -> stores guarded.

#define CK       8
#define TILE_OC  64
#define THREADS  256

typedef unsigned long long ull;

__device__ __forceinline__ ull pk(float lo, float hi) {
    ull r;
    asm("mov.b64 %0, {%1, %2};" : "=l"(r) : "f"(lo), "f"(hi));
    return r;
}
__device__ __forceinline__ void upk(float& lo, float& hi, ull v) {
    asm("mov.b64 {%0, %1}, %2;" : "=f"(lo), "=f"(hi) : "l"(v));
}
__device__ __forceinline__ void fma2(ull& d, ull a, ull b) {
    asm("fma.rn.f32x2 %0, %1, %2, %0;" : "+l"(d) : "l"(a), "l"(b));
}

struct RowP { ull A, B, C, S1, S2; };  // pairs (q0,q1)(q2,q3)(q4,q5)(q1,q2)(q3,q4)

__global__ __launch_bounds__(THREADS, 2)
void conv3x3_kernel(const float* __restrict__ x,
                    const float* __restrict__ wgt,
                    const float* __restrict__ bias,
                    float* __restrict__ out)
{
    // sW[r][oc]: r = c*9 + kh*3 + kw (72 rows), oc padded 64->80 words
    // (320B row stride: 16B-aligned float4 reads, benign STS pattern).
    __shared__ float sW[CK * 9][80];
    // Input tile 8 rows + halo = 10 rows, 16 cols + halo = 18, padded to 20
    // words (80B stride -> x LDS.128 exactly 2-phase across the warp).
    __shared__ float sIn[CK][10][20];

    const int tid = threadIdx.x;
    const int pxg  = tid & 15;         // 4 rowg x 4 cg
    const int ocg  = tid >> 4;         // 0..15
    const int rowg = pxg >> 2;         // 0..3
    const int cg   = pxg & 3;          // 0..3
    const int y0   = rowg * 2;         // local output rows y0, y0+1
    const int px4  = cg * 4;           // local output col base (0,4,8,12)
    const int ocb  = ocg * 4;

    const int rt = blockIdx.x >> 2;    // 0..6 row tile
    const int ct = blockIdx.x & 3;     // 0..3 col tile
    const int o0 = blockIdx.y * TILE_OC;
    const int n  = blockIdx.z;

    const int h0  = rt * 8;
    const int wc0 = ct * 16;

    const float* xn = x + (size_t)n * 128 * 56 * 56;

    ull acc[4][2][2];                  // [oc][oy][px-pair]
#pragma unroll
    for (int i = 0; i < 4; ++i)
#pragma unroll
        for (int oy = 0; oy < 2; ++oy) {
            acc[i][oy][0] = 0ull; acc[i][oy][1] = 0ull;
        }

    for (int c0 = 0; c0 < 128; c0 += CK) {
        // ---- stage input tile (CK x 10 x 18, zero-padded halo) ----
#pragma unroll
        for (int idx = tid; idx < CK * 10 * 18; idx += THREADS) {
            int c   = idx / 180;
            int rem = idx - c * 180;
            int r   = rem / 18;
            int q   = rem - r * 18;
            int gh = h0 - 1 + r;
            int gw = wc0 - 1 + q;
            float v = 0.0f;
            if ((unsigned)gh < 56u && (unsigned)gw < 56u)
                v = xn[((size_t)(c0 + c) * 56 + gh) * 56 + gw];
            sIn[c][r][q] = v;
        }
        // ---- stage weights (coalesced 72-float gmem runs per oc) ----
#pragma unroll
        for (int idx = tid; idx < CK * 9 * TILE_OC; idx += THREADS) {
            int oc = idx / (CK * 9);
            int r  = idx - oc * (CK * 9);
            sW[r][oc] = wgt[(size_t)(o0 + oc) * 1152 + c0 * 9 + r];
        }
        __syncthreads();

#pragma unroll
        for (int c = 0; c < CK; ++c) {
            // Load + pack 4 patch rows (rows y0..y0+3, cols px4..px4+5)
            RowP R[4];
#pragma unroll
            for (int d = 0; d < 4; ++d) {
                const float* row = &sIn[c][y0 + d][px4];
                const float4 f = *(const float4*)row;
                const float2 g = *(const float2*)(row + 4);
                R[d].A  = pk(f.x, f.y);
                R[d].B  = pk(f.z, f.w);
                R[d].C  = pk(g.x, g.y);
                R[d].S1 = pk(f.y, f.z);
                R[d].S2 = pk(f.w, g.x);
            }
#pragma unroll
            for (int kh = 0; kh < 3; ++kh) {
#pragma unroll
                for (int kw = 0; kw < 3; ++kw) {
                    const float4 wv = *(const float4*)&sW[c * 9 + kh * 3 + kw][ocb];
                    const ull w0 = pk(wv.x, wv.x);
                    const ull w1 = pk(wv.y, wv.y);
                    const ull w2 = pk(wv.z, wv.z);
                    const ull w3 = pk(wv.w, wv.w);
#pragma unroll
                    for (int oy = 0; oy < 2; ++oy) {
                        const RowP& r = R[oy + kh];
                        const ull b0 = (kw == 0) ? r.A : (kw == 1) ? r.S1 : r.B;
                        const ull b1 = (kw == 0) ? r.B : (kw == 1) ? r.S2 : r.C;
                        fma2(acc[0][oy][0], w0, b0); fma2(acc[0][oy][1], w0, b1);
                        fma2(acc[1][oy][0], w1, b0); fma2(acc[1][oy][1], w1, b1);
                        fma2(acc[2][oy][0], w2, b0); fma2(acc[2][oy][1], w2, b1);
                        fma2(acc[3][oy][0], w3, b0); fma2(acc[3][oy][1], w3, b1);
                    }
                }
            }
        }
        __syncthreads();
    }

    // ---- epilogue: unpack, +bias, guarded float4 stores ----
    const bool colok = (wc0 + px4 + 3) < 56;   // whole float4 in range or skip
#pragma unroll
    for (int i = 0; i < 4; ++i) {
        const int o = o0 + ocb + i;
        const float b = __ldg(&bias[o]);
        float* op = out + (((size_t)n * 256 + o) * 56 + h0) * 56 + wc0 + px4;
#pragma unroll
        for (int oy = 0; oy < 2; ++oy) {
            float4 v;
            upk(v.x, v.y, acc[i][oy][0]);
            upk(v.z, v.w, acc[i][oy][1]);
            v.x += b; v.y += b; v.z += b; v.w += b;
            if (colok)
                *(float4*)(op + (y0 + oy) * 56) = v;
        }
    }
}

extern "C" void kernel_launch(void* const* d_in, const int* in_sizes, int n_in,
                              void* d_out, int out_size)
{
    const float* x    = (const float*)d_in[0];
    const float* w    = (const float*)d_in[1];
    const float* bias = (const float*)d_in[2];
    float* out        = (float*)d_out;

    dim3 grid(28, 4, 32);   // (7 row-tiles * 4 col-tiles, oc-tiles, images)
    conv3x3_kernel<<<grid, THREADS>>>(x, w, bias, out);
}

// round 3
// speedup vs baseline: 1.6205x; 1.4269x over previous
#include <cuda_runtime.h>
#include <cuda_bf16.h>

// Dense 3x3 conv, NCHW fp32, stride 1, pad 1, + bias.
// x: (32,128,56,56), w: (256,128,3,3), bias: (256) -> out: (32,256,56,56)
//
// R3: f32x2 pairs over ADJACENT OUTPUT CHANNELS.
//  - a-operand (w[oc],w[oc+1]) is a free register-pair reinterpret of LDS.128
//  - b-operand (xs,xs) replicated via one mov.b64 per use
//  - thread microtile: 8 oc x (2x4) px = 64 outputs, 0.33 smem-B/FLOP
//  - block: 64 oc x 8x28 spatial, 224 threads; 7x2 tiles cover 56x56 exactly
//    (zero waste, no store guards)

#define CK       8
#define TILE_OC  64
#define THREADS  224

typedef unsigned long long ull;

__device__ __forceinline__ ull pk2(float v) {
    ull r;
    asm("mov.b64 %0, {%1, %1};" : "=l"(r) : "f"(v));
    return r;
}
__device__ __forceinline__ void upk(float& lo, float& hi, ull v) {
    asm("mov.b64 {%0, %1}, %2;" : "=f"(lo), "=f"(hi) : "l"(v));
}
__device__ __forceinline__ void fma2(ull& d, ull a, ull b) {
    asm("fma.rn.f32x2 %0, %1, %2, %0;" : "+l"(d) : "l"(a), "l"(b));
}

__global__ __launch_bounds__(THREADS, 2)
void conv3x3_kernel(const float* __restrict__ x,
                    const float* __restrict__ wgt,
                    const float* __restrict__ bias,
                    float* __restrict__ out)
{
    // sW[r][oc]: r = c*9 + kh*3 + kw (72 rows), oc padded 64->68
    // (272B row stride: 16B-aligned ulonglong2/LDS.128 reads).
    __shared__ float sW[CK * 9][68];
    // Input tile: 8 rows + halo = 10, 28 cols + halo = 30, padded to 36
    // words (144B stride: 16B aligned, 4-bank skew per row -> the 4 row
    // groups of a warp hit distinct banks).
    __shared__ float sIn[CK][10][36];

    const int tid = threadIdx.x;
    const int pxi = tid % 28;
    const int ocg = tid / 28;          // 0..7
    const int ct  = pxi % 7;           // col-thread
    const int rt_ = pxi / 7;           // row-thread 0..3
    const int px0 = ct * 4;            // local output col base (0..24)
    const int y0  = rt_ * 2;           // local output row base (0,2,4,6)
    const int ocb = ocg * 8;

    const int brow = blockIdx.x >> 1;  // 0..6
    const int bcol = blockIdx.x & 1;   // 0..1
    const int o0   = blockIdx.y * TILE_OC;
    const int n    = blockIdx.z;

    const int h0 = brow * 8;
    const int w0 = bcol * 28;

    const float* xn = x + (size_t)n * 128 * 56 * 56;

    ull acc[4][2][4];                  // [oc-pair][oy][ox]
#pragma unroll
    for (int p = 0; p < 4; ++p)
#pragma unroll
        for (int oy = 0; oy < 2; ++oy)
#pragma unroll
            for (int ox = 0; ox < 4; ++ox) acc[p][oy][ox] = 0ull;

    for (int c0 = 0; c0 < 128; c0 += CK) {
        // ---- stage input tile (CK x 10 x 30, zero-padded halo) ----
        for (int idx = tid; idx < CK * 10 * 30; idx += THREADS) {
            int c   = idx / 300;
            int rem = idx - c * 300;
            int r   = rem / 30;
            int q   = rem - r * 30;
            int gh = h0 - 1 + r;
            int gw = w0 - 1 + q;
            float v = 0.0f;
            if ((unsigned)gh < 56u && (unsigned)gw < 56u)
                v = xn[((size_t)(c0 + c) * 56 + gh) * 56 + gw];
            sIn[c][r][q] = v;
        }
        // ---- stage weights (coalesced 72-float gmem runs per oc) ----
        for (int idx = tid; idx < CK * 9 * TILE_OC; idx += THREADS) {
            int oc = idx / (CK * 9);
            int r  = idx - oc * (CK * 9);
            sW[r][oc] = wgt[(size_t)(o0 + oc) * 1152 + c0 * 9 + r];
        }
        __syncthreads();

#pragma unroll
        for (int c = 0; c < CK; ++c) {
            // patch: rows y0..y0+3, cols px0..px0+5 (held in regs)
            float P[4][6];
#pragma unroll
            for (int d = 0; d < 4; ++d) {
                const float* row = &sIn[c][y0 + d][px0];
                const float4 a = *(const float4*)row;
                const float2 b = *(const float2*)(row + 4);
                P[d][0] = a.x; P[d][1] = a.y; P[d][2] = a.z;
                P[d][3] = a.w; P[d][4] = b.x; P[d][5] = b.y;
            }
#pragma unroll
            for (int kh = 0; kh < 3; ++kh) {
#pragma unroll
                for (int kw = 0; kw < 3; ++kw) {
                    const float* wr = &sW[c * 9 + kh * 3 + kw][ocb];
                    const ulonglong2 wA = *(const ulonglong2*)wr;       // (oc0,oc1)(oc2,oc3)
                    const ulonglong2 wB = *(const ulonglong2*)(wr + 4); // (oc4,oc5)(oc6,oc7)
#pragma unroll
                    for (int oy = 0; oy < 2; ++oy) {
#pragma unroll
                        for (int ox = 0; ox < 4; ++ox) {
                            const ull xx = pk2(P[oy + kh][ox + kw]);
                            fma2(acc[0][oy][ox], wA.x, xx);
                            fma2(acc[1][oy][ox], wA.y, xx);
                            fma2(acc[2][oy][ox], wB.x, xx);
                            fma2(acc[3][oy][ox], wB.y, xx);
                        }
                    }
                }
            }
        }
        __syncthreads();
    }

    // ---- epilogue: unpack per-oc, +bias, float4 stores (all in-bounds) ----
#pragma unroll
    for (int p = 0; p < 4; ++p) {
        const int olo = o0 + ocb + 2 * p;
        const float blo = __ldg(&bias[olo]);
        const float bhi = __ldg(&bias[olo + 1]);
        float* oplo = out + (((size_t)n * 256 + olo) * 56 + h0 + y0) * 56 + w0 + px0;
        float* ophi = oplo + (size_t)56 * 56;
#pragma unroll
        for (int oy = 0; oy < 2; ++oy) {
            float4 vlo, vhi;
            upk(vlo.x, vhi.x, acc[p][oy][0]);
            upk(vlo.y, vhi.y, acc[p][oy][1]);
            upk(vlo.z, vhi.z, acc[p][oy][2]);
            upk(vlo.w, vhi.w, acc[p][oy][3]);
            vlo.x += blo; vlo.y += blo; vlo.z += blo; vlo.w += blo;
            vhi.x += bhi; vhi.y += bhi; vhi.z += bhi; vhi.w += bhi;
            *(float4*)(oplo + oy * 56) = vlo;
            *(float4*)(ophi + oy * 56) = vhi;
        }
    }
}

extern "C" void kernel_launch(void* const* d_in, const int* in_sizes, int n_in,
                              void* d_out, int out_size)
{
    const float* x    = (const float*)d_in[0];
    const float* w    = (const float*)d_in[1];
    const float* bias = (const float*)d_in[2];
    float* out        = (float*)d_out;

    dim3 grid(14, 4, 32);   // (7 row-tiles * 2 col-tiles, oc-tiles, images)
    conv3x3_kernel<<<grid, THREADS>>>(x, w, bias, out);
}